// round 4
// baseline (speedup 1.0000x reference)
#include <cuda_runtime.h>
#include <cuda_fp16.h>
#include <cstdint>

#define KDIM      4096
#define NDIM      16384
#define NCTA_FEAT 128                 // output features per CTA
#define KCHUNK    32                  // k elements (ints) per pipeline stage
#define NCHUNKS   (KDIM / KCHUNK)     // 128
#define SROW      36                  // padded ints per row in smem (144B)
#define NSTAGES   10
#define STAGE_INTS (NCTA_FEAT * SROW) // 4608 ints = 18432 B
#define SMEM_BYTES (NSTAGES * STAGE_INTS * 4)   // 184320 B

__device__ __forceinline__ void cp_async16(uint32_t dst, const void* src) {
    asm volatile("cp.async.cg.shared.global [%0], [%1], 16;" :: "r"(dst), "l"(src));
}
__device__ __forceinline__ void cp_commit() {
    asm volatile("cp.async.commit_group;");
}
template <int N>
__device__ __forceinline__ void cp_wait() {
    asm volatile("cp.async.wait_group %0;" :: "n"(N));
}

// pack two f32 into f16x2: low half = lo, high half = hi (single fp16 rounding)
__device__ __forceinline__ uint32_t pack_h2(float hi, float lo) {
    uint32_t r;
    asm("cvt.rn.f16x2.f32 %0, %1, %2;" : "=r"(r) : "f"(hi), "f"(lo));
    return r;
}
// dequant: fp16(int * scale), exact f32 product, one rounding — matches reference
__device__ __forceinline__ uint32_t i2h2s(int lo, int hi, float s) {
    return pack_h2((float)hi * s, (float)lo * s);
}

__device__ __forceinline__ void mma16816(float c[4],
                                         uint32_t a0, uint32_t a1,
                                         uint32_t a2, uint32_t a3,
                                         uint32_t b0, uint32_t b1) {
    asm volatile(
        "mma.sync.aligned.m16n8k16.row.col.f32.f16.f16.f32 "
        "{%0,%1,%2,%3}, {%4,%5,%6,%7}, {%8,%9}, {%0,%1,%2,%3};"
        : "+f"(c[0]), "+f"(c[1]), "+f"(c[2]), "+f"(c[3])
        : "r"(a0), "r"(a1), "r"(a2), "r"(a3), "r"(b0), "r"(b1));
}

extern __shared__ int smem[];

__global__ void __launch_bounds__(256, 1)
w8linear_kernel(const float* __restrict__ X,   // [32, 4096]  f32 (fp16 values)
                const int*   __restrict__ W,   // [16384, 4096] int32 (int8 values)
                const float* __restrict__ S,   // [16384] f32 (fp16 values)
                const float* __restrict__ Bi,  // [16384] f32 (fp16 values)
                float*       __restrict__ O)   // [32, 16384] f32
{
    const int tid  = threadIdx.x;
    const int warp = tid >> 5;
    const int lane = tid & 31;
    const int g    = lane >> 2;     // 0..7
    const int t    = lane & 3;      // 0..3

    const int nbase = blockIdx.x * NCTA_FEAT + warp * 16;
    const int n0 = nbase + g;
    const int n1 = nbase + 8 + g;

    const uint32_t smem_u32 = (uint32_t)__cvta_generic_to_shared(smem);

    // ---- producer mapping: 1024 x 16B copies per stage, 4 per thread ----
    const int pr = tid >> 1;              // smem/weight row 0..127
    const int sb = (tid & 1) * 4;         // starting 16B segment (0 or 4)
    const int*     gsrc_base = W + (size_t)(blockIdx.x * NCTA_FEAT + pr) * KDIM + sb * 4;
    const uint32_t sdst_row  = smem_u32 + (uint32_t)(pr * SROW + sb * 4) * 4;

    auto issue_stage = [&](int slot, int chunk) {
        const int*     src = gsrc_base + chunk * KCHUNK;
        const uint32_t dst = sdst_row + (uint32_t)(slot * STAGE_INTS) * 4;
#pragma unroll
        for (int j = 0; j < 4; j++)
            cp_async16(dst + j * 16, src + j * 4);
    };

    const float s0 = S[n0];
    const float s1 = S[n1];

    float acc[2][2][4];
#pragma unroll
    for (int mt = 0; mt < 2; mt++)
#pragma unroll
        for (int nt = 0; nt < 2; nt++)
#pragma unroll
            for (int i = 0; i < 4; i++) acc[mt][nt][i] = 0.0f;

    // smem row bases for this thread's two weight rows
    const int srow0 = (warp * 16 + g) * SROW + 2 * t;
    const int srow1 = (warp * 16 + 8 + g) * SROW + 2 * t;

    auto compute_chunk = [&](int slot, int chunk) {
        const int sbase = slot * STAGE_INTS;
#pragma unroll
        for (int s_ = 0; s_ < 2; s_++) {
            const int koff = s_ * 16;
            // B fragments from smem (LDS.64)
            const int2 w00 = *(const int2*)&smem[sbase + srow0 + koff];
            const int2 w01 = *(const int2*)&smem[sbase + srow0 + koff + 8];
            const int2 w10 = *(const int2*)&smem[sbase + srow1 + koff];
            const int2 w11 = *(const int2*)&smem[sbase + srow1 + koff + 8];

            // A fragments from global (L1/L2-hot), convert f32 -> f16x2
            const int kk = chunk * KCHUNK + koff + 2 * t;
            uint32_t A0[4], A1[4];
#pragma unroll
            for (int r = 0; r < 4; r++) {
                const float2 f0 = *(const float2*)(X + (size_t)(g + 8 * r) * KDIM + kk);
                const float2 f1 = *(const float2*)(X + (size_t)(g + 8 * r) * KDIM + kk + 8);
                A0[r] = pack_h2(f0.y, f0.x);
                A1[r] = pack_h2(f1.y, f1.x);
            }

            const uint32_t b00 = i2h2s(w00.x, w00.y, s0);
            const uint32_t b01 = i2h2s(w01.x, w01.y, s0);
            const uint32_t b10 = i2h2s(w10.x, w10.y, s1);
            const uint32_t b11 = i2h2s(w11.x, w11.y, s1);

            mma16816(acc[0][0], A0[0], A0[1], A1[0], A1[1], b00, b01);
            mma16816(acc[0][1], A0[0], A0[1], A1[0], A1[1], b10, b11);
            mma16816(acc[1][0], A0[2], A0[3], A1[2], A1[3], b00, b01);
            mma16816(acc[1][1], A0[2], A0[3], A1[2], A1[3], b10, b11);
        }
    };

    // ---- prologue: fill NSTAGES-1 stages ----
#pragma unroll
    for (int s = 0; s < NSTAGES - 1; s++) {
        issue_stage(s, s);
        cp_commit();
    }

    // ---- main pipeline ----
    int slot_c = 0;                 // consume slot
    int slot_p = NSTAGES - 1;       // produce slot
#pragma unroll 1
    for (int c = 0; c < NCHUNKS; c++) {
        cp_wait<NSTAGES - 2>();
        __syncthreads();

        const int nxt = c + NSTAGES - 1;
        if (nxt < NCHUNKS) issue_stage(slot_p, nxt);
        cp_commit();

        compute_chunk(slot_c, c);

        if (++slot_c == NSTAGES) slot_c = 0;
        if (++slot_p == NSTAGES) slot_p = 0;
    }

    // ---- epilogue: emulate reference rounding: fp16(dot) + fp16(bias) in fp16 ----
#pragma unroll
    for (int mt = 0; mt < 2; mt++) {
#pragma unroll
        for (int nt = 0; nt < 2; nt++) {
            const int f  = nbase + nt * 8 + 2 * t;
            const int r0 = mt * 16 + g;
            const int r1 = r0 + 8;
            const __half bx = __float2half_rn(Bi[f]);
            const __half by = __float2half_rn(Bi[f + 1]);

            const __half h00 = __hadd(__float2half_rn(acc[mt][nt][0]), bx);
            const __half h01 = __hadd(__float2half_rn(acc[mt][nt][1]), by);
            const __half h10 = __hadd(__float2half_rn(acc[mt][nt][2]), bx);
            const __half h11 = __hadd(__float2half_rn(acc[mt][nt][3]), by);

            float2 o0 = make_float2(__half2float(h00), __half2float(h01));
            float2 o1 = make_float2(__half2float(h10), __half2float(h11));
            *(float2*)(O + (size_t)r0 * NDIM + f) = o0;
            *(float2*)(O + (size_t)r1 * NDIM + f) = o1;
        }
    }
}

extern "C" void kernel_launch(void* const* d_in, const int* in_sizes, int n_in,
                              void* d_out, int out_size) {
    (void)in_sizes; (void)n_in; (void)out_size;
    const float* x = (const float*)d_in[0];
    const int*   w = (const int*)d_in[1];
    const float* s = (const float*)d_in[2];
    const float* b = (const float*)d_in[3];
    float*       o = (float*)d_out;

    cudaFuncSetAttribute(w8linear_kernel,
                         cudaFuncAttributeMaxDynamicSharedMemorySize, SMEM_BYTES);
    w8linear_kernel<<<NDIM / NCTA_FEAT, 256, SMEM_BYTES>>>(x, w, s, b, o);
}

// round 5
// speedup vs baseline: 1.9685x; 1.9685x over previous
#include <cuda_runtime.h>
#include <cuda_fp16.h>
#include <cstdint>

#define KDIM     4096
#define NDIM     16384
#define NCHUNKS  128                 // k-chunks of 32 ints
#define NSTAGES  10
#define SROW     40                  // ints per smem row (160B, conflict-free)
#define STAGE_I  (16 * SROW)         // 640 ints per warp-stage
#define WARP_I   (NSTAGES * STAGE_I) // 6400 ints per warp
#define SMEM_BYTES (8 * WARP_I * 4)  // 204800 B

// X pre-packed to fp16 in mma-fragment order:
// XC[(kb*32 + lane)*8 + i], i order:
//   (g,lo)(g+8,lo)(g,hi)(g+8,hi)(g+16,lo)(g+24,lo)(g+16,hi)(g+24,hi)
__device__ uint32_t XC[(KDIM / 16) * 32 * 8];   // 65536 u32 = 256 KB

__device__ __forceinline__ void cp_async16(uint32_t dst, const void* src) {
    asm volatile("cp.async.cg.shared.global [%0], [%1], 16;" :: "r"(dst), "l"(src));
}
__device__ __forceinline__ void cp_commit() {
    asm volatile("cp.async.commit_group;");
}
template <int N>
__device__ __forceinline__ void cp_wait() {
    asm volatile("cp.async.wait_group %0;" :: "n"(N));
}

__device__ __forceinline__ uint32_t pack_h2(float hi, float lo) {
    uint32_t r;
    asm("cvt.rn.f16x2.f32 %0, %1, %2;" : "=r"(r) : "f"(hi), "f"(lo));
    return r;
}
// fp16(int * scale): exact f32 product, single fp16 rounding — matches reference
__device__ __forceinline__ uint32_t i2h2s(int lo, int hi, float s) {
    return pack_h2((float)hi * s, (float)lo * s);
}

__device__ __forceinline__ void mma16816(float c[4],
                                         uint32_t a0, uint32_t a1,
                                         uint32_t a2, uint32_t a3,
                                         uint32_t b0, uint32_t b1) {
    asm volatile(
        "mma.sync.aligned.m16n8k16.row.col.f32.f16.f16.f32 "
        "{%0,%1,%2,%3}, {%4,%5,%6,%7}, {%8,%9}, {%0,%1,%2,%3};"
        : "+f"(c[0]), "+f"(c[1]), "+f"(c[2]), "+f"(c[3])
        : "r"(a0), "r"(a1), "r"(a2), "r"(a3), "r"(b0), "r"(b1));
}

// ---------------- prologue kernel: pack X (f32, fp16-valued) into XC ----------------
__global__ void __launch_bounds__(256) convert_x_kernel(const float* __restrict__ X) {
    const int tid  = blockIdx.x * 256 + threadIdx.x;   // 8192 threads
    const int kb   = tid >> 5;
    const int lane = tid & 31;
    const int g    = lane >> 2;
    const int t    = lane & 3;
    const int c0   = kb * 16 + 2 * t;
    const int c1   = c0 + 8;

    uint32_t* dst = XC + (size_t)(kb * 32 + lane) * 8;
    const int r0 = g, r1 = g + 8, r2 = g + 16, r3 = g + 24;

    #define PK(r, c) pack_h2(X[(size_t)(r) * KDIM + (c) + 1], X[(size_t)(r) * KDIM + (c)])
    dst[0] = PK(r0, c0); dst[1] = PK(r1, c0); dst[2] = PK(r0, c1); dst[3] = PK(r1, c1);
    dst[4] = PK(r2, c0); dst[5] = PK(r3, c0); dst[6] = PK(r2, c1); dst[7] = PK(r3, c1);
    #undef PK
}

// ---------------- main GEMM: warp-autonomous cp.async pipelines ----------------
extern __shared__ int smem[];

__global__ void __launch_bounds__(256, 1)
w8linear_kernel(const int*   __restrict__ W,   // [16384, 4096] int32 (int8-valued)
                const float* __restrict__ S,   // [16384] f32
                const float* __restrict__ Bi,  // [16384] f32
                float*       __restrict__ O)   // [32, 16384] f32
{
    const int tid  = threadIdx.x;
    const int warp = tid >> 5;
    const int lane = tid & 31;
    const int g    = lane >> 2;
    const int t    = lane & 3;

    const int nbase = blockIdx.x * 128 + warp * 16;
    const int n0 = nbase + g;
    const int n1 = nbase + 8 + g;

    // per-warp smem region
    int* const wsm = smem + warp * WARP_I;
    const uint32_t wsm_u32 = (uint32_t)__cvta_generic_to_shared(wsm);

    // producer mapping: warp loads its own 16 rows x 128B per chunk.
    // lane -> row (lane>>1), 64B half (lane&1); 4 x cp.async16 per thread.
    const int prow = lane >> 1;
    const int phal = lane & 1;
    const int* const gsrc = W + (size_t)(nbase + prow) * KDIM + phal * 16;
    const uint32_t sdst = wsm_u32 + (uint32_t)(prow * SROW + phal * 16) * 4;

    auto issue_stage = [&](int slot, int chunk) {
        const int*     src = gsrc + chunk * 32;
        const uint32_t dst = sdst + (uint32_t)(slot * STAGE_I) * 4;
#pragma unroll
        for (int j = 0; j < 4; j++)
            cp_async16(dst + j * 16, src + j * 4);
    };

    const float s0 = S[n0];
    const float s1 = S[n1];

    float acc[2][2][4];
#pragma unroll
    for (int mt = 0; mt < 2; mt++)
#pragma unroll
        for (int nt = 0; nt < 2; nt++)
#pragma unroll
            for (int i = 0; i < 4; i++) acc[mt][nt][i] = 0.0f;

    const int srow0 = g * SROW + 2 * t;           // consumer smem row bases
    const int srow1 = (8 + g) * SROW + 2 * t;

    auto compute_chunk = [&](int slot, int chunk) {
        const int sbase = slot * STAGE_I;
#pragma unroll
        for (int s_ = 0; s_ < 2; s_++) {
            const int kb   = chunk * 2 + s_;
            const int koff = s_ * 16;

            // A fragments: 2x LDG.128, L1/L2-hot, already fp16-packed
            const uint32_t* ap = XC + (size_t)(kb * 32 + lane) * 8;
            const uint4 p0 = __ldg((const uint4*)ap);
            const uint4 p1 = __ldg((const uint4*)(ap + 4));

            // B fragments from warp-local smem (conflict-free, LDS.64)
            const int2 w00 = *(const int2*)&wsm[sbase + srow0 + koff];
            const int2 w01 = *(const int2*)&wsm[sbase + srow0 + koff + 8];
            const int2 w10 = *(const int2*)&wsm[sbase + srow1 + koff];
            const int2 w11 = *(const int2*)&wsm[sbase + srow1 + koff + 8];

            const uint32_t b00 = i2h2s(w00.x, w00.y, s0);
            const uint32_t b01 = i2h2s(w01.x, w01.y, s0);
            const uint32_t b10 = i2h2s(w10.x, w10.y, s1);
            const uint32_t b11 = i2h2s(w11.x, w11.y, s1);

            mma16816(acc[0][0], p0.x, p0.y, p0.z, p0.w, b00, b01);
            mma16816(acc[0][1], p0.x, p0.y, p0.z, p0.w, b10, b11);
            mma16816(acc[1][0], p1.x, p1.y, p1.z, p1.w, b00, b01);
            mma16816(acc[1][1], p1.x, p1.y, p1.z, p1.w, b10, b11);
        }
    };

    // prologue: fill 9 stages (one commit group per stage)
#pragma unroll
    for (int s = 0; s < NSTAGES - 1; s++) {
        issue_stage(s, s);
        cp_commit();
    }

    // main loop: NO __syncthreads — per-warp pipeline, per-thread groups
    int slot_c = 0, slot_p = NSTAGES - 1;
#pragma unroll 1
    for (int c = 0; c < NCHUNKS; c++) {
        cp_wait<NSTAGES - 2>();
        __syncwarp();

        const int nxt = c + NSTAGES - 1;
        if (nxt < NCHUNKS) issue_stage(slot_p, nxt);
        cp_commit();                       // commit every iter (keeps group math exact)

        compute_chunk(slot_c, c);

        slot_c = (slot_c + 1 == NSTAGES) ? 0 : slot_c + 1;
        slot_p = (slot_p + 1 == NSTAGES) ? 0 : slot_p + 1;
    }

    // epilogue: fp16(acc) + fp16(bias) in fp16, store f32 (matches reference rounding)
#pragma unroll
    for (int mt = 0; mt < 2; mt++) {
#pragma unroll
        for (int nt = 0; nt < 2; nt++) {
            const int f  = nbase + nt * 8 + 2 * t;
            const int r0 = mt * 16 + g;
            const int r1 = r0 + 8;
            const __half bx = __float2half_rn(Bi[f]);
            const __half by = __float2half_rn(Bi[f + 1]);

            const __half h00 = __hadd(__float2half_rn(acc[mt][nt][0]), bx);
            const __half h01 = __hadd(__float2half_rn(acc[mt][nt][1]), by);
            const __half h10 = __hadd(__float2half_rn(acc[mt][nt][2]), bx);
            const __half h11 = __hadd(__float2half_rn(acc[mt][nt][3]), by);

            *(float2*)(O + (size_t)r0 * NDIM + f) =
                make_float2(__half2float(h00), __half2float(h01));
            *(float2*)(O + (size_t)r1 * NDIM + f) =
                make_float2(__half2float(h10), __half2float(h11));
        }
    }
}

extern "C" void kernel_launch(void* const* d_in, const int* in_sizes, int n_in,
                              void* d_out, int out_size) {
    (void)in_sizes; (void)n_in; (void)out_size;
    const float* x = (const float*)d_in[0];
    const int*   w = (const int*)d_in[1];
    const float* s = (const float*)d_in[2];
    const float* b = (const float*)d_in[3];
    float*       o = (float*)d_out;

    convert_x_kernel<<<32, 256>>>(x);

    static int configured = 0;
    if (!configured) {
        cudaFuncSetAttribute(w8linear_kernel,
                             cudaFuncAttributeMaxDynamicSharedMemorySize, SMEM_BYTES);
        configured = 1;
    }
    w8linear_kernel<<<NDIM / 128, 256, SMEM_BYTES>>>(w, s, b, o);
}

// round 6
// speedup vs baseline: 2.3228x; 1.1800x over previous
#include <cuda_runtime.h>
#include <cuda_fp16.h>
#include <cstdint>

#define KDIM     4096
#define NDIM     16384
#define NCHUNKS  128                 // k-chunks of 32 ints
#define NSTAGES  5
#define SROW     40                  // ints per smem row (160B, conflict-free)
#define STAGE_I  (16 * SROW)         // 640 ints per warp-stage (2560 B)
#define WARP_I   (NSTAGES * STAGE_I) // 3200 ints per warp
#define NWARPS   16
#define SMEM_BYTES (NWARPS * WARP_I * 4)   // 204800 B

// X pre-packed to fp16 in mma-fragment order:
// XC[(kb*32 + lane)*8 + i], i order:
//   (g,lo)(g+8,lo)(g,hi)(g+8,hi)(g+16,lo)(g+24,lo)(g+16,hi)(g+24,hi)
__device__ uint32_t XC[(KDIM / 16) * 32 * 8];   // 256 KB

__device__ __forceinline__ void cp_async16(uint32_t dst, const void* src) {
    asm volatile("cp.async.cg.shared.global [%0], [%1], 16;" :: "r"(dst), "l"(src));
}
__device__ __forceinline__ void cp_commit() {
    asm volatile("cp.async.commit_group;");
}
template <int N>
__device__ __forceinline__ void cp_wait() {
    asm volatile("cp.async.wait_group %0;" :: "n"(N));
}

__device__ __forceinline__ uint32_t pack_h2(float hi, float lo) {
    uint32_t r;
    asm("cvt.rn.f16x2.f32 %0, %1, %2;" : "=r"(r) : "f"(hi), "f"(lo));
    return r;
}

// Exact dequant, bit-identical to reference fp16(v) * fp16(s):
// byte0 of each int32 -> fp16 magic (1024+128+v), subtract 1152 (exact), HMUL2 by s.
__device__ __forceinline__ uint32_t dq(int2 w, __half2 s2) {
    uint32_t r;
    asm("prmt.b32 %0, %1, %2, 0x0400;" : "=r"(r) : "r"(w.x), "r"(w.y));
    r = (r & 0x00FF00FFu) ^ 0x64806480u;
    __half2 h = __hsub2(*reinterpret_cast<__half2*>(&r),
                        __half2half2(__ushort_as_half((unsigned short)0x6480)));
    h = __hmul2(h, s2);
    return *reinterpret_cast<uint32_t*>(&h);
}

__device__ __forceinline__ void mma16816(float c[4],
                                         uint32_t a0, uint32_t a1,
                                         uint32_t a2, uint32_t a3,
                                         uint32_t b0, uint32_t b1) {
    asm volatile(
        "mma.sync.aligned.m16n8k16.row.col.f32.f16.f16.f32 "
        "{%0,%1,%2,%3}, {%4,%5,%6,%7}, {%8,%9}, {%0,%1,%2,%3};"
        : "+f"(c[0]), "+f"(c[1]), "+f"(c[2]), "+f"(c[3])
        : "r"(a0), "r"(a1), "r"(a2), "r"(a3), "r"(b0), "r"(b1));
}

// ---------------- prologue kernel: pack X (f32, fp16-valued) into XC ----------------
__global__ void __launch_bounds__(256) convert_x_kernel(const float* __restrict__ X) {
    const int tid  = blockIdx.x * 256 + threadIdx.x;   // 8192 threads
    const int kb   = tid >> 5;
    const int lane = tid & 31;
    const int g    = lane >> 2;
    const int t    = lane & 3;
    const int c0   = kb * 16 + 2 * t;
    const int c1   = c0 + 8;

    uint32_t* dst = XC + (size_t)(kb * 32 + lane) * 8;
    const int r0 = g, r1 = g + 8, r2 = g + 16, r3 = g + 24;

    #define PK(r, c) pack_h2(X[(size_t)(r) * KDIM + (c) + 1], X[(size_t)(r) * KDIM + (c)])
    dst[0] = PK(r0, c0); dst[1] = PK(r1, c0); dst[2] = PK(r0, c1); dst[3] = PK(r1, c1);
    dst[4] = PK(r2, c0); dst[5] = PK(r3, c0); dst[6] = PK(r2, c1); dst[7] = PK(r3, c1);
    #undef PK
}

// ---------------- main GEMM: 16 warps, warp pairs split k by chunk parity ----------------
extern __shared__ int smem[];

__global__ void __launch_bounds__(512, 1)
w8linear_kernel(const int*   __restrict__ W,   // [16384, 4096] int32 (int8-valued)
                const float* __restrict__ S,   // [16384] f32 (fp16-valued)
                const float* __restrict__ Bi,  // [16384] f32 (fp16-valued)
                float*       __restrict__ O)   // [32, 16384] f32
{
    const int tid  = threadIdx.x;
    const int warp = tid >> 5;
    const int lane = tid & 31;
    const int g    = lane >> 2;
    const int t    = lane & 3;
    const int fg   = warp >> 1;       // feature group 0..7
    const int par  = warp & 1;        // k-parity of this warp

    const int nbase = blockIdx.x * 128 + fg * 16;
    const int n0 = nbase + g;
    const int n1 = nbase + 8 + g;

    // per-warp smem ring
    int* const wsm = smem + warp * WARP_I;
    const uint32_t wsm_u32 = (uint32_t)__cvta_generic_to_shared(wsm);

    // producer mapping: lane -> row (lane>>1), 64B half (lane&1); 4 cp.async16/thread
    const int prow = lane >> 1;
    const int phal = lane & 1;
    const int* const gsrc = W + (size_t)(nbase + prow) * KDIM + phal * 16;
    const uint32_t sdst = wsm_u32 + (uint32_t)(prow * SROW + phal * 16) * 4;

    auto issue_stage = [&](int slot, int chunk) {
        const int*     src = gsrc + chunk * 32;
        const uint32_t dst = sdst + (uint32_t)(slot * STAGE_I) * 4;
#pragma unroll
        for (int j = 0; j < 4; j++)
            cp_async16(dst + j * 16, src + j * 4);
    };

    const __half  hs0 = __float2half_rn(S[n0]);
    const __half  hs1 = __float2half_rn(S[n1]);
    const __half2 s0_2 = __half2half2(hs0);
    const __half2 s1_2 = __half2half2(hs1);

    float acc[2][2][4];
#pragma unroll
    for (int mt = 0; mt < 2; mt++)
#pragma unroll
        for (int nt = 0; nt < 2; nt++)
#pragma unroll
            for (int i = 0; i < 4; i++) acc[mt][nt][i] = 0.0f;

    const int srow0 = g * SROW + 2 * t;
    const int srow1 = (8 + g) * SROW + 2 * t;

    // A register double-buffer: [buf][substep][mtile]
    uint4 Ab[2][2][2];
    auto load_A = [&](int buf, int chunk) {
#pragma unroll
        for (int s_ = 0; s_ < 2; s_++) {
            const uint32_t* ap = XC + (size_t)((chunk * 2 + s_) * 32 + lane) * 8;
            Ab[buf][s_][0] = __ldg((const uint4*)ap);
            Ab[buf][s_][1] = __ldg((const uint4*)(ap + 4));
        }
    };

    auto compute_chunk = [&](int slot, int buf) {
        const int sbase = slot * STAGE_I;
#pragma unroll
        for (int s_ = 0; s_ < 2; s_++) {
            const int koff = s_ * 16;
            const int2 w00 = *(const int2*)&wsm[sbase + srow0 + koff];
            const int2 w01 = *(const int2*)&wsm[sbase + srow0 + koff + 8];
            const int2 w10 = *(const int2*)&wsm[sbase + srow1 + koff];
            const int2 w11 = *(const int2*)&wsm[sbase + srow1 + koff + 8];

            const uint32_t b00 = dq(w00, s0_2);
            const uint32_t b01 = dq(w01, s0_2);
            const uint32_t b10 = dq(w10, s1_2);
            const uint32_t b11 = dq(w11, s1_2);

            const uint4 p0 = Ab[buf][s_][0];
            const uint4 p1 = Ab[buf][s_][1];
            mma16816(acc[0][0], p0.x, p0.y, p0.z, p0.w, b00, b01);
            mma16816(acc[0][1], p0.x, p0.y, p0.z, p0.w, b10, b11);
            mma16816(acc[1][0], p1.x, p1.y, p1.z, p1.w, b00, b01);
            mma16816(acc[1][1], p1.x, p1.y, p1.z, p1.w, b10, b11);
        }
    };

    // prologue: fill 4 stages with this warp's chunks (par, par+2, par+4, par+6)
#pragma unroll
    for (int s = 0; s < NSTAGES - 1; s++) {
        issue_stage(s, par + 2 * s);
        cp_commit();
    }
    load_A(0, par);

    // main loop: 64 chunks per warp, stride 2; no __syncthreads anywhere
    int slot_c = 0, slot_p = NSTAGES - 1;
#pragma unroll 2
    for (int i = 0; i < 64; i++) {
        const int c = par + 2 * i;
        const int buf = i & 1;

        cp_wait<NSTAGES - 2>();
        __syncwarp();

        if (i + NSTAGES - 1 < 64) issue_stage(slot_p, c + 2 * (NSTAGES - 1));
        cp_commit();

        if (i + 1 < 64) load_A(buf ^ 1, c + 2);

        compute_chunk(slot_c, buf);

        slot_c = (slot_c + 1 == NSTAGES) ? 0 : slot_c + 1;
        slot_p = (slot_p + 1 == NSTAGES) ? 0 : slot_p + 1;
    }

    // ---- pair reduction: parity-1 warp dumps f32 accs into its own ring space ----
    float* const afl = &acc[0][0][0];
    if (par == 1) {
        float* dst = (float*)wsm;
#pragma unroll
        for (int i = 0; i < 16; i++) dst[lane * 16 + i] = afl[i];
    }
    __syncthreads();

    if (par == 0) {
        const float* src = (const float*)(smem + (warp + 1) * WARP_I);
#pragma unroll
        for (int i = 0; i < 16; i++) afl[i] += src[lane * 16 + i];

        // epilogue: fp16(dot) + fp16(bias) in fp16, store f32 (reference rounding)
#pragma unroll
        for (int mt = 0; mt < 2; mt++) {
#pragma unroll
            for (int nt = 0; nt < 2; nt++) {
                const int f  = nbase + nt * 8 + 2 * t;
                const int r0 = mt * 16 + g;
                const int r1 = r0 + 8;
                const __half bx = __float2half_rn(Bi[f]);
                const __half by = __float2half_rn(Bi[f + 1]);

                const __half h00 = __hadd(__float2half_rn(acc[mt][nt][0]), bx);
                const __half h01 = __hadd(__float2half_rn(acc[mt][nt][1]), by);
                const __half h10 = __hadd(__float2half_rn(acc[mt][nt][2]), bx);
                const __half h11 = __hadd(__float2half_rn(acc[mt][nt][3]), by);

                *(float2*)(O + (size_t)r0 * NDIM + f) =
                    make_float2(__half2float(h00), __half2float(h01));
                *(float2*)(O + (size_t)r1 * NDIM + f) =
                    make_float2(__half2float(h10), __half2float(h11));
            }
        }
    }
}

extern "C" void kernel_launch(void* const* d_in, const int* in_sizes, int n_in,
                              void* d_out, int out_size) {
    (void)in_sizes; (void)n_in; (void)out_size;
    const float* x = (const float*)d_in[0];
    const int*   w = (const int*)d_in[1];
    const float* s = (const float*)d_in[2];
    const float* b = (const float*)d_in[3];
    float*       o = (float*)d_out;

    convert_x_kernel<<<32, 256>>>(x);

    cudaFuncSetAttribute(w8linear_kernel,
                         cudaFuncAttributeMaxDynamicSharedMemorySize, SMEM_BYTES);
    w8linear_kernel<<<NDIM / 128, 512, SMEM_BYTES>>>(w, s, b, o);
}